// round 8
// baseline (speedup 1.0000x reference)
#include <cuda_runtime.h>

// LogSpaceSinkhorn: 64 independent 1024x1024 matrices.
// ls = x - u_i - v_j representation; 12 streaming LSE reduction passes + 1 output pass.
// All log-space math in base 2 (y = x * log2(e)) so LSE uses raw MUFU EX2/LG2,
// and no max-subtraction is needed (values bounded, fp32 range is ample).

#define NN 1024
#define BMAX 64

static __device__ __align__(16) float g_u[BMAX * NN];
static __device__ __align__(16) float g_v[BMAX * NN];

__device__ __forceinline__ float ex2f(float x) {
    float y; asm("ex2.approx.ftz.f32 %0, %1;" : "=f"(y) : "f"(x)); return y;
}
__device__ __forceinline__ float lg2f(float x) {
    float y; asm("lg2.approx.ftz.f32 %0, %1;" : "=f"(y) : "f"(x)); return y;
}

__device__ __forceinline__ float get_scale(const float* __restrict__ tau) {
    // y = log_scores * (log2(e) / max(tau, 0.1))
    return 1.4426950408889634f / fmaxf(*tau, 0.1f);
}

// u_i = log2( sum_j 2^(a_ij*scale - v_j) ).  One warp per row (contiguous 4KB),
// values held in registers, single global read per element.
__global__ void __launch_bounds__(256) row_lse(
    const float* __restrict__ a, const float* __restrict__ tau, int use_v)
{
    int gw   = (blockIdx.x * blockDim.x + threadIdx.x) >> 5;  // global row id
    int lane = threadIdx.x & 31;
    int m    = gw >> 10;

    const float* __restrict__ arow = a + ((size_t)gw << 10);
    const float* __restrict__ vrow = g_v + (m << 10);
    float scale = get_scale(tau);

    float s = 0.f;
#pragma unroll
    for (int jj = 0; jj < 8; ++jj) {
        int j = jj * 128 + lane * 4;
        float4 av = *reinterpret_cast<const float4*>(arow + j);
        float vx = 0.f, vy = 0.f, vz = 0.f, vw = 0.f;
        if (use_v) {
            float4 vv = *reinterpret_cast<const float4*>(vrow + j);
            vx = vv.x; vy = vv.y; vz = vv.z; vw = vv.w;
        }
        s += ex2f(fmaf(av.x, scale, -vx));
        s += ex2f(fmaf(av.y, scale, -vy));
        s += ex2f(fmaf(av.z, scale, -vz));
        s += ex2f(fmaf(av.w, scale, -vw));
    }
#pragma unroll
    for (int o = 16; o; o >>= 1) s += __shfl_xor_sync(0xffffffffu, s, o);
    if (lane == 0) g_u[gw] = lg2f(s);
}

// v_j = log2( sum_i 2^(a_ij*scale - u_i) ).  128 threads = 128 consecutive
// columns per CTA (coalesced 512B per row), stream 1024 rows, u staged in smem.
// final_mode: write w_j = 0.5*(v5_j + v6_j) in place (for the symmetric final).
__global__ void __launch_bounds__(128) col_lse(
    const float* __restrict__ a, const float* __restrict__ tau, int final_mode)
{
    __shared__ float su[NN];
    int m   = blockIdx.x >> 3;
    int col = ((blockIdx.x & 7) << 7) + threadIdx.x;

    for (int i = threadIdx.x; i < NN; i += 128) su[i] = g_u[(m << 10) + i];
    __syncthreads();

    float scale = get_scale(tau);
    const float* __restrict__ base = a + ((size_t)m << 20) + col;

    float s = 0.f;
#pragma unroll 8
    for (int i = 0; i < NN; ++i)
        s += ex2f(fmaf(base[(size_t)i << 10], scale, -su[i]));

    float lse = lg2f(s);
    int o = (m << 10) + col;
    g_v[o] = final_mode ? 0.5f * (g_v[o] + lse) : lse;
}

// out_ij = 2^(a_ij*scale - u6_i - w_j), w = 0.5*(v5+v6) already in g_v.
__global__ void __launch_bounds__(256) finalize_k(
    const float* __restrict__ a, const float* __restrict__ tau,
    float* __restrict__ out)
{
    int idx = blockIdx.x * blockDim.x + threadIdx.x;   // float4 index
    size_t e = (size_t)idx << 2;
    int m   = (int)(e >> 20);
    int row = (int)(e >> 10) & 1023;
    int j   = (int)(e & 1023);

    float scale = get_scale(tau);
    float uv = g_u[(m << 10) + row];
    float4 wv = *reinterpret_cast<const float4*>(&g_v[(m << 10) + j]);
    float4 av = *reinterpret_cast<const float4*>(a + e);

    float4 r;
    r.x = ex2f(fmaf(av.x, scale, -(uv + wv.x)));
    r.y = ex2f(fmaf(av.y, scale, -(uv + wv.y)));
    r.z = ex2f(fmaf(av.z, scale, -(uv + wv.z)));
    r.w = ex2f(fmaf(av.w, scale, -(uv + wv.w)));
    *reinterpret_cast<float4*>(out + e) = r;
}

extern "C" void kernel_launch(void* const* d_in, const int* in_sizes, int n_in,
                              void* d_out, int out_size)
{
    const float* a   = (const float*)d_in[0];
    const float* tau = (const float*)d_in[1];
    float* out       = (float*)d_out;

    int b = in_sizes[0] / (NN * NN);          // 64 matrices
    dim3 rgrid(b * NN / 8), rblock(256);      // 8 rows (warps) per CTA
    dim3 cgrid(b * 8),      cblock(128);      // 8 column-blocks per matrix
    dim3 fgrid(in_sizes[0] / 1024), fblock(256);

    // 5 Sinkhorn iterations
    for (int it = 0; it < 5; ++it) {
        row_lse<<<rgrid, rblock>>>(a, tau, it > 0);   // u <- rowLSE(x - v)
        col_lse<<<cgrid, cblock>>>(a, tau, 0);        // v <- colLSE(x - u)
    }
    // Symmetric final: u6 from v5; then g_v <- 0.5*(v5 + v6)
    row_lse<<<rgrid, rblock>>>(a, tau, 1);
    col_lse<<<cgrid, cblock>>>(a, tau, 1);
    // out = 2^(x - u6 - w)
    finalize_k<<<fgrid, fblock>>>(a, tau, out);
}

// round 9
// speedup vs baseline: 1.3776x; 1.3776x over previous
#include <cuda_runtime.h>

// LogSpaceSinkhorn: 64 independent 1024x1024 fp32 matrices.
// Potentials form: ls = x*scale - u_i - v_j (base-2 log space), matrix read-only.
// 12 streaming LSE reduction passes + 1 output pass = 13x256MB read + 256MB write.

#define NN 1024
#define BMAX 64

static __device__ __align__(16) float g_u[BMAX * NN];
static __device__ __align__(16) float g_v[BMAX * NN];

__device__ __forceinline__ float ex2f(float x) {
    float y; asm("ex2.approx.ftz.f32 %0, %1;" : "=f"(y) : "f"(x)); return y;
}
__device__ __forceinline__ float lg2f(float x) {
    float y; asm("lg2.approx.ftz.f32 %0, %1;" : "=f"(y) : "f"(x)); return y;
}

__device__ __forceinline__ float get_scale(const float* __restrict__ tau) {
    // y = log_scores * (log2(e) / max(tau, 0.1))
    return 1.4426950408889634f / fmaxf(*tau, 0.1f);
}

// u_i = log2( sum_j 2^(a_ij*scale - v_j) ).  One warp per row (contiguous 4KB),
// single global read per element, warp shuffle reduce.
__global__ void __launch_bounds__(256) row_lse(
    const float* __restrict__ a, const float* __restrict__ tau, int use_v)
{
    int gw   = (blockIdx.x * blockDim.x + threadIdx.x) >> 5;  // global row id
    int lane = threadIdx.x & 31;
    int m    = gw >> 10;

    const float* __restrict__ arow = a + ((size_t)gw << 10);
    const float* __restrict__ vrow = g_v + (m << 10);
    float scale = get_scale(tau);

    float s = 0.f;
#pragma unroll
    for (int jj = 0; jj < 8; ++jj) {
        int j = jj * 128 + lane * 4;
        float4 av = *reinterpret_cast<const float4*>(arow + j);
        float vx = 0.f, vy = 0.f, vz = 0.f, vw = 0.f;
        if (use_v) {
            float4 vv = *reinterpret_cast<const float4*>(vrow + j);
            vx = vv.x; vy = vv.y; vz = vv.z; vw = vv.w;
        }
        s += ex2f(fmaf(av.x, scale, -vx));
        s += ex2f(fmaf(av.y, scale, -vy));
        s += ex2f(fmaf(av.z, scale, -vz));
        s += ex2f(fmaf(av.w, scale, -vw));
    }
#pragma unroll
    for (int o = 16; o; o >>= 1) s += __shfl_xor_sync(0xffffffffu, s, o);
    if (lane == 0) g_u[gw] = lg2f(s);
}

// v_j = log2( sum_i 2^(a_ij*scale - u_i) ).
// 512 threads/CTA: thread = (row-group g in [0,16), column-quad q in [0,32)).
// Each thread float4-loads its 4 columns over 64 rows; smem reduce across the
// 16 row-groups; lane-quad threads emit 4 LSEs. 128 columns per CTA, 8 CTAs
// per matrix column dim, grid = B*8.
// final_mode: g_v <- 0.5*(g_v + lse) (symmetric final blend).
__global__ void __launch_bounds__(512) col_lse(
    const float* __restrict__ a, const float* __restrict__ tau, int final_mode)
{
    __shared__ float  su[NN];          // 4 KB
    __shared__ float4 red[16][32];     // 8 KB

    int m    = blockIdx.x >> 3;
    int cblk = (blockIdx.x & 7) << 7;          // base column of this CTA (128 cols)
    int tid  = threadIdx.x;
    int q    = tid & 31;                        // column quad 0..31
    int g    = tid >> 5;                        // row group  0..15
    int col  = cblk + q * 4;

    // stage u for this matrix
#pragma unroll
    for (int k = 0; k < 2; ++k) su[tid + k * 512] = g_u[(m << 10) + tid + k * 512];
    __syncthreads();

    float scale = get_scale(tau);
    const float* __restrict__ base =
        a + ((size_t)m << 20) + ((size_t)(g * 64) << 10) + col;
    const float* __restrict__ ug = su + g * 64;

    float4 s = {0.f, 0.f, 0.f, 0.f};
#pragma unroll 8
    for (int i = 0; i < 64; ++i) {
        float4 av = *reinterpret_cast<const float4*>(base + ((size_t)i << 10));
        float u = ug[i];
        s.x += ex2f(fmaf(av.x, scale, -u));
        s.y += ex2f(fmaf(av.y, scale, -u));
        s.z += ex2f(fmaf(av.z, scale, -u));
        s.w += ex2f(fmaf(av.w, scale, -u));
    }
    red[g][q] = s;
    __syncthreads();

    if (g == 0) {
        float4 acc = red[0][q];
#pragma unroll
        for (int k = 1; k < 16; ++k) {
            float4 r = red[k][q];
            acc.x += r.x; acc.y += r.y; acc.z += r.z; acc.w += r.w;
        }
        float4 lse;
        lse.x = lg2f(acc.x); lse.y = lg2f(acc.y);
        lse.z = lg2f(acc.z); lse.w = lg2f(acc.w);
        int o = (m << 10) + col;
        if (final_mode) {
            float4 prev = *reinterpret_cast<const float4*>(&g_v[o]);
            lse.x = 0.5f * (prev.x + lse.x);
            lse.y = 0.5f * (prev.y + lse.y);
            lse.z = 0.5f * (prev.z + lse.z);
            lse.w = 0.5f * (prev.w + lse.w);
        }
        *reinterpret_cast<float4*>(&g_v[o]) = lse;
    }
}

// out_ij = 2^(a_ij*scale - u6_i - w_j), w = 0.5*(v5+v6) already in g_v.
__global__ void __launch_bounds__(256) finalize_k(
    const float* __restrict__ a, const float* __restrict__ tau,
    float* __restrict__ out)
{
    int idx = blockIdx.x * blockDim.x + threadIdx.x;   // float4 index
    size_t e = (size_t)idx << 2;
    int m   = (int)(e >> 20);
    int row = (int)(e >> 10) & 1023;
    int j   = (int)(e & 1023);

    float scale = get_scale(tau);
    float uv = g_u[(m << 10) + row];
    float4 wv = *reinterpret_cast<const float4*>(&g_v[(m << 10) + j]);
    float4 av = *reinterpret_cast<const float4*>(a + e);

    float4 r;
    r.x = ex2f(fmaf(av.x, scale, -(uv + wv.x)));
    r.y = ex2f(fmaf(av.y, scale, -(uv + wv.y)));
    r.z = ex2f(fmaf(av.z, scale, -(uv + wv.z)));
    r.w = ex2f(fmaf(av.w, scale, -(uv + wv.w)));
    *reinterpret_cast<float4*>(out + e) = r;
}

extern "C" void kernel_launch(void* const* d_in, const int* in_sizes, int n_in,
                              void* d_out, int out_size)
{
    const float* a   = (const float*)d_in[0];
    const float* tau = (const float*)d_in[1];
    float* out       = (float*)d_out;

    int b = in_sizes[0] / (NN * NN);          // 64 matrices
    dim3 rgrid(b * NN / 8), rblock(256);      // 8 rows (warps) per CTA
    dim3 cgrid(b * 8),      cblock(512);      // 8 column-blocks per matrix
    dim3 fgrid(in_sizes[0] / 1024), fblock(256);

    // 5 Sinkhorn iterations
    for (int it = 0; it < 5; ++it) {
        row_lse<<<rgrid, rblock>>>(a, tau, it > 0);   // u <- rowLSE(x - v)
        col_lse<<<cgrid, cblock>>>(a, tau, 0);        // v <- colLSE(x - u)
    }
    // Symmetric final: u6 from v5; then g_v <- 0.5*(v5 + v6)
    row_lse<<<rgrid, rblock>>>(a, tau, 1);
    col_lse<<<cgrid, cblock>>>(a, tau, 1);
    // out = 2^(x - u6 - w)
    finalize_k<<<fgrid, fblock>>>(a, tau, out);
}

// round 10
// speedup vs baseline: 1.9746x; 1.4333x over previous
#include <cuda_runtime.h>

// LogSpaceSinkhorn: 64 independent 1024x1024 fp32 matrices.
// Potentials form: ls = x*scale - u_i - v_j (base-2 log space); matrix read-only.
// L2-resident chunking: process 16 matrices (64MB, fits 126MB L2) through all
// 13 passes before moving to the next chunk -> DRAM read traffic ~1x instead of 13x.

#define NN 1024
#define BMAX 64
#define CHUNK 16

static __device__ __align__(16) float g_u[BMAX * NN];
static __device__ __align__(16) float g_v[BMAX * NN];

__device__ __forceinline__ float ex2f(float x) {
    float y; asm("ex2.approx.ftz.f32 %0, %1;" : "=f"(y) : "f"(x)); return y;
}
__device__ __forceinline__ float lg2f(float x) {
    float y; asm("lg2.approx.ftz.f32 %0, %1;" : "=f"(y) : "f"(x)); return y;
}
__device__ __forceinline__ float get_scale(const float* __restrict__ tau) {
    return 1.4426950408889634f / fmaxf(*tau, 0.1f);   // log2(e)/max(tau,0.1)
}

// u_i = log2( sum_j 2^(a_ij*scale - v_j) ). One warp per row, float4 loads,
// shuffle reduce. Operates on matrices [mbase, mbase+nm).
__global__ void __launch_bounds__(256) row_lse(
    const float* __restrict__ a, const float* __restrict__ tau,
    int use_v, int mbase)
{
    int gw   = (blockIdx.x * blockDim.x + threadIdx.x) >> 5;  // row within chunk
    int lane = threadIdx.x & 31;
    int m    = mbase + (gw >> 10);

    const float* __restrict__ arow = a + ((size_t)m << 20) + ((size_t)(gw & 1023) << 10);
    const float* __restrict__ vrow = g_v + (m << 10);
    float scale = get_scale(tau);

    float s = 0.f;
#pragma unroll
    for (int jj = 0; jj < 8; ++jj) {
        int j = jj * 128 + lane * 4;
        float4 av = *reinterpret_cast<const float4*>(arow + j);
        float vx = 0.f, vy = 0.f, vz = 0.f, vw = 0.f;
        if (use_v) {
            float4 vv = *reinterpret_cast<const float4*>(vrow + j);
            vx = vv.x; vy = vv.y; vz = vv.z; vw = vv.w;
        }
        s += ex2f(fmaf(av.x, scale, -vx));
        s += ex2f(fmaf(av.y, scale, -vy));
        s += ex2f(fmaf(av.z, scale, -vz));
        s += ex2f(fmaf(av.w, scale, -vw));
    }
#pragma unroll
    for (int o = 16; o; o >>= 1) s += __shfl_xor_sync(0xffffffffu, s, o);
    if (lane == 0) g_u[(m << 10) + (gw & 1023)] = lg2f(s);
}

// v_j = log2( sum_i 2^(a_ij*scale - u_i) ).
// 256 threads/CTA = 8 column-quads (32 cols) x 32 row-groups (32 rows each).
// 32 CTAs per matrix. smem reduce across row-groups, 8 threads emit 32 LSEs.
// final_mode: g_v <- 0.5*(g_v + lse).
__global__ void __launch_bounds__(256, 6) col_lse(
    const float* __restrict__ a, const float* __restrict__ tau,
    int final_mode, int mbase)
{
    __shared__ float  su[NN];         // 4 KB
    __shared__ float4 red[32][8];     // 4 KB

    int m    = mbase + (blockIdx.x >> 5);
    int cblk = (blockIdx.x & 31) << 5;          // 32 columns per CTA
    int tid  = threadIdx.x;
    int q    = tid & 7;                          // column quad 0..7
    int g    = tid >> 3;                         // row group  0..31
    int col  = cblk + q * 4;

#pragma unroll
    for (int k = 0; k < 4; ++k) su[tid + k * 256] = g_u[(m << 10) + tid + k * 256];
    __syncthreads();

    float scale = get_scale(tau);
    const float* __restrict__ base =
        a + ((size_t)m << 20) + ((size_t)(g * 32) << 10) + col;
    const float* __restrict__ ug = su + g * 32;

    float4 s = {0.f, 0.f, 0.f, 0.f};
#pragma unroll 8
    for (int i = 0; i < 32; ++i) {
        float4 av = *reinterpret_cast<const float4*>(base + ((size_t)i << 10));
        float u = ug[i];
        s.x += ex2f(fmaf(av.x, scale, -u));
        s.y += ex2f(fmaf(av.y, scale, -u));
        s.z += ex2f(fmaf(av.z, scale, -u));
        s.w += ex2f(fmaf(av.w, scale, -u));
    }
    red[g][q] = s;
    __syncthreads();

    if (tid < 8) {
        float4 acc = red[0][tid];
#pragma unroll
        for (int k = 1; k < 32; ++k) {
            float4 r = red[k][tid];
            acc.x += r.x; acc.y += r.y; acc.z += r.z; acc.w += r.w;
        }
        float4 lse;
        lse.x = lg2f(acc.x); lse.y = lg2f(acc.y);
        lse.z = lg2f(acc.z); lse.w = lg2f(acc.w);
        int o = (m << 10) + cblk + tid * 4;
        if (final_mode) {
            float4 prev = *reinterpret_cast<const float4*>(&g_v[o]);
            lse.x = 0.5f * (prev.x + lse.x);
            lse.y = 0.5f * (prev.y + lse.y);
            lse.z = 0.5f * (prev.z + lse.z);
            lse.w = 0.5f * (prev.w + lse.w);
        }
        *reinterpret_cast<float4*>(&g_v[o]) = lse;
    }
}

// out_ij = 2^(a_ij*scale - u6_i - w_j), w = 0.5*(v5+v6) already in g_v.
__global__ void __launch_bounds__(256) finalize_k(
    const float* __restrict__ a, const float* __restrict__ tau,
    float* __restrict__ out, int mbase)
{
    size_t e = ((size_t)(blockIdx.x * blockDim.x + threadIdx.x) << 2)
             + ((size_t)mbase << 20);
    int m   = (int)(e >> 20);
    int row = (int)(e >> 10) & 1023;
    int j   = (int)(e & 1023);

    float scale = get_scale(tau);
    float uv = g_u[(m << 10) + row];
    float4 wv = *reinterpret_cast<const float4*>(&g_v[(m << 10) + j]);
    float4 av = *reinterpret_cast<const float4*>(a + e);

    float4 r;
    r.x = ex2f(fmaf(av.x, scale, -(uv + wv.x)));
    r.y = ex2f(fmaf(av.y, scale, -(uv + wv.y)));
    r.z = ex2f(fmaf(av.z, scale, -(uv + wv.z)));
    r.w = ex2f(fmaf(av.w, scale, -(uv + wv.w)));
    *reinterpret_cast<float4*>(out + e) = r;
}

extern "C" void kernel_launch(void* const* d_in, const int* in_sizes, int n_in,
                              void* d_out, int out_size)
{
    const float* a   = (const float*)d_in[0];
    const float* tau = (const float*)d_in[1];
    float* out       = (float*)d_out;

    int b = in_sizes[0] / (NN * NN);          // 64 matrices

    for (int c0 = 0; c0 < b; c0 += CHUNK) {
        int nm = (b - c0 < CHUNK) ? (b - c0) : CHUNK;
        dim3 rgrid(nm * NN / 8), rblock(256);   // 8 rows (warps) per CTA
        dim3 cgrid(nm * 32),    cblock(256);    // 32 column-blocks per matrix
        dim3 fgrid(nm * 1024),  fblock(256);    // nm*1M elems / 4 / 256

        for (int it = 0; it < 5; ++it) {
            row_lse<<<rgrid, rblock>>>(a, tau, it > 0, c0);  // u <- rowLSE(x - v)
            col_lse<<<cgrid, cblock>>>(a, tau, 0, c0);       // v <- colLSE(x - u)
        }
        // Symmetric final: u6 from v5; then g_v <- 0.5*(v5 + v6)
        row_lse<<<rgrid, rblock>>>(a, tau, 1, c0);
        col_lse<<<cgrid, cblock>>>(a, tau, 1, c0);
        // out = 2^(x - u6 - w) while the chunk is still L2-hot
        finalize_k<<<fgrid, fblock>>>(a, tau, out, c0);
    }
}